// round 4
// baseline (speedup 1.0000x reference)
#include <cuda_runtime.h>

// Census loss, pair-symmetric, scalar math, MUFU-bound design.
// total = sum_{unordered pairs (a,b), off in H(24)} t * (v(a)+v(b))
// t = 1 - 0.1*rcp(0.1+e^2), e = cx-cy, c = d*rsqrt(7.29+d^2) with d = 3*(g(b)-g(a)).
// Output = total / (49*8*256*256).

#define IMG   256
#define IMG2  65536
#define SWP   40          // padded shared row width (floats)
#define SROWS 14          // TROWS + 6
#define TCOLS 32
#define TROWS 8

__device__ __forceinline__ float frsqrt_a(float x){ float r; asm("rsqrt.approx.f32 %0, %1;" : "=f"(r) : "f"(x)); return r; }
__device__ __forceinline__ float frcp_a  (float x){ float r; asm("rcp.approx.f32 %0, %1;"   : "=f"(r) : "f"(x)); return r; }

// rc = 1/(0.1+e^2) for one unordered pair
__device__ __forceinline__ float pair_rc(float nbx, float nby, float cenx, float ceny)
{
    float dX = nbx - cenx;
    float dY = nby - ceny;
    float cx = dX * frsqrt_a(fmaf(dX, dX, 7.29f));
    float cy = dY * frsqrt_a(fmaf(dY, dY, 7.29f));
    float e  = cx - cy;
    return frcp_a(fmaf(e, e, 0.1f));
}

__global__ __launch_bounds__(128, 8)
void census_loss_kernel(const float* __restrict__ x,
                        const float* __restrict__ y,
                        float* __restrict__ out)
{
    __shared__ __align__(8) float sgx[SROWS * SWP];
    __shared__ __align__(8) float sgy[SROWS * SWP];

    const int b    = blockIdx.z;
    const int row0 = blockIdx.y * TROWS;
    const int col0 = blockIdx.x * TCOLS;
    const int tid  = threadIdx.y * 16 + threadIdx.x;

    const float* xb = x + (size_t)b * 3 * IMG2;
    const float* yb = y + (size_t)b * 3 * IMG2;

    // 3*grayscale tile + halo (zero outside image; weight 0 kills those pairs)
    for (int i = tid; i < SROWS * SWP; i += 128) {
        int lr = i / SWP;
        int lc = i - lr * SWP;
        int gr = row0 - 3 + lr;
        int gc = col0 - 3 + lc;
        float gx = 0.f, gy = 0.f;
        if ((unsigned)gr < 256u && (unsigned)gc < 256u) {
            int o = gr * IMG + gc;
            gx = xb[o] + xb[o + IMG2] + xb[o + 2 * IMG2];
            gy = yb[o] + yb[o + IMG2] + yb[o + 2 * IMG2];
        }
        sgx[i] = gx;
        sgy[i] = gy;
    }
    __syncthreads();

    const int tx = threadIdx.x;     // 0..15  -> pixel cols 2tx, 2tx+1 (tile-local)
    const int ty = threadIdx.y;     // 0..7

    // float2 view; elem k of this window covers tile-local cols (2tx-3+2k, 2tx-2+2k)
    const float2* bx2 = (const float2*)sgx + (ty + 3) * (SWP / 2) + tx;
    const float2* by2 = (const float2*)sgy + (ty + 3) * (SWP / 2) + tx;

    float2 ex1 = bx2[1], ex2 = bx2[2], ex3 = bx2[3];
    float2 ey1 = by2[1], ey2 = by2[2], ey3 = by2[3];
    const float c0x = ex1.y, c1x = ex2.x;   // centers, x image
    const float c0y = ey1.y, c1y = ey2.x;   // centers, y image

    const bool interior = (blockIdx.x - 1u < 6u) & (blockIdx.y - 1u < 30u);

    float res;
    if (interior) {
        float accr = 0.f;
        // dy = 0 (right half only): p0 dx=1,2,3 ; p1 dx=1,2,3
        accr += pair_rc(ex2.x, ey2.x, c0x, c0y);
        accr += pair_rc(ex2.y, ey2.y, c0x, c0y);
        accr += pair_rc(ex3.x, ey3.x, c0x, c0y);
        accr += pair_rc(ex2.y, ey2.y, c1x, c1y);
        accr += pair_rc(ex3.x, ey3.x, c1x, c1y);
        accr += pair_rc(ex3.y, ey3.y, c1x, c1y);
#pragma unroll
        for (int dy = 1; dy < 4; dy++) {
            const float2* rx = bx2 + dy * (SWP / 2);
            const float2* ry = by2 + dy * (SWP / 2);
            float2 a0 = rx[0], a1 = rx[1], a2 = rx[2], a3 = rx[3];
            float2 b0 = ry[0], b1 = ry[1], b2 = ry[2], b3 = ry[3];
            float vx[8] = {a0.x, a0.y, a1.x, a1.y, a2.x, a2.y, a3.x, a3.y};
            float vy[8] = {b0.x, b0.y, b1.x, b1.y, b2.x, b2.y, b3.x, b3.y};
#pragma unroll
            for (int j = 0; j < 7; j++) {
                accr += pair_rc(vx[j],     vy[j],     c0x, c0y);
                accr += pair_rc(vx[j + 1], vy[j + 1], c1x, c1y);
            }
        }
        // 48 pairs, weight 2 each: sum w*t = 2*(48 - 0.1*accr)
        res = fmaf(-0.2f, accr, 96.f);
    } else {
        const int R = row0 + ty;
        const int C = col0 + 2 * tx;
        float vrow[4], vcw[8];
#pragma unroll
        for (int d = 0; d < 4; d++) vrow[d] = ((unsigned)(R + d - 3) < 250u) ? 1.f : 0.f;
#pragma unroll
        for (int j = 0; j < 8; j++) vcw[j] = ((unsigned)(C + j - 6) < 250u) ? 1.f : 0.f;
        const float va0 = vrow[0] * vcw[3];
        const float va1 = vrow[0] * vcw[4];

        float accw = 0.f, accr = 0.f;
        {   // dy = 0
            float rc, w;
            rc = pair_rc(ex2.x, ey2.x, c0x, c0y); w = fmaf(vrow[0], vcw[4], va0); accw += w; accr = fmaf(w, rc, accr);
            rc = pair_rc(ex2.y, ey2.y, c0x, c0y); w = fmaf(vrow[0], vcw[5], va0); accw += w; accr = fmaf(w, rc, accr);
            rc = pair_rc(ex3.x, ey3.x, c0x, c0y); w = fmaf(vrow[0], vcw[6], va0); accw += w; accr = fmaf(w, rc, accr);
            rc = pair_rc(ex2.y, ey2.y, c1x, c1y); w = fmaf(vrow[0], vcw[5], va1); accw += w; accr = fmaf(w, rc, accr);
            rc = pair_rc(ex3.x, ey3.x, c1x, c1y); w = fmaf(vrow[0], vcw[6], va1); accw += w; accr = fmaf(w, rc, accr);
            rc = pair_rc(ex3.y, ey3.y, c1x, c1y); w = fmaf(vrow[0], vcw[7], va1); accw += w; accr = fmaf(w, rc, accr);
        }
#pragma unroll
        for (int dy = 1; dy < 4; dy++) {
            const float2* rx = bx2 + dy * (SWP / 2);
            const float2* ry = by2 + dy * (SWP / 2);
            float2 a0 = rx[0], a1 = rx[1], a2 = rx[2], a3 = rx[3];
            float2 b0 = ry[0], b1 = ry[1], b2 = ry[2], b3 = ry[3];
            float vx[8] = {a0.x, a0.y, a1.x, a1.y, a2.x, a2.y, a3.x, a3.y};
            float vy[8] = {b0.x, b0.y, b1.x, b1.y, b2.x, b2.y, b3.x, b3.y};
#pragma unroll
            for (int j = 0; j < 7; j++) {
                float rc, w;
                rc = pair_rc(vx[j], vy[j], c0x, c0y);
                w  = fmaf(vrow[dy], vcw[j], va0);  accw += w; accr = fmaf(w, rc, accr);
                rc = pair_rc(vx[j + 1], vy[j + 1], c1x, c1y);
                w  = fmaf(vrow[dy], vcw[j + 1], va1); accw += w; accr = fmaf(w, rc, accr);
            }
        }
        res = fmaf(-0.1f, accr, accw);
    }

    // warp + block reduction (4 warps)
#pragma unroll
    for (int s = 16; s > 0; s >>= 1)
        res += __shfl_xor_sync(0xFFFFFFFFu, res, s);

    __shared__ float wsum[4];
    if ((tid & 31) == 0) wsum[tid >> 5] = res;
    __syncthreads();
    if (tid < 4) {
        float v = wsum[tid];
        v += __shfl_xor_sync(0xFu, v, 2);
        v += __shfl_xor_sync(0xFu, v, 1);
        if (tid == 0)
            atomicAdd(out, v * (1.f / 25690112.f));   // 1/(49*8*256*256)
    }
}

extern "C" void kernel_launch(void* const* d_in, const int* in_sizes, int n_in,
                              void* d_out, int out_size)
{
    const float* x = (const float*)d_in[0];
    const float* y = (const float*)d_in[1];
    float* out = (float*)d_out;

    cudaMemsetAsync(out, 0, sizeof(float));

    dim3 block(16, 8, 1);
    dim3 grid(IMG / TCOLS, IMG / TROWS, 8);   // 8 x 32 x 8 = 2048 blocks
    census_loss_kernel<<<grid, block>>>(x, y, out);
}